// round 11
// baseline (speedup 1.0000x reference)
#include <cuda_runtime.h>
#include <cuda_fp16.h>
#include <cstdint>

// ============================================================
// TorchRandomProject: out[4096,4096] = x[4096,2048] @ matrix[0][4096,2048]^T
// fp16 HMMA (same 10-bit mantissa as tf32 => same rel_err), fp32 accum.
// R11: exact revert to R9 champion (128x128, 2 CTA/SM, 3-stage, unroll-1
// chunk loop, batched LDSM->MMA body) + per-CTA kk phase rotation
// (decorrelate the two co-resident CTAs' smem/tensor issue phases).
// R10's intra-warp LDSM reordering regressed (broke ptxas scheduling) and
// is NOT carried forward.
// ============================================================

#define B_DIM   4096
#define K_DIM   2048
#define O_DIM   4096

// 32MB device scratch for fp16 operands
__device__ __half g_xh[(size_t)B_DIM * K_DIM];
__device__ __half g_wh[(size_t)O_DIM * K_DIM];

// ---------------- tile config ----------------
#define BM 128
#define BN 128
#define BK 64                       // K halfs per chunk (128B row)
#define NSTAGE 3
#define NCHUNK (K_DIM / BK)         // 32
#define A_BYTES (BM * BK * 2)       // 16384
#define B_BYTES (BN * BK * 2)       // 16384
#define STAGE_BYTES (A_BYTES + B_BYTES)      // 32768
#define SMEM_TOTAL (NSTAGE * STAGE_BYTES)    // 98304 (2 CTAs = 192KB/SM)

// ---------------- PTX helpers ----------------
__device__ __forceinline__ uint32_t smem_u32(const void* p) {
    uint32_t a;
    asm("{ .reg .u64 t; cvta.to.shared.u64 t, %1; cvt.u32.u64 %0, t; }" : "=r"(a) : "l"(p));
    return a;
}

__device__ __forceinline__ void cp_async16(uint32_t dst, const void* src) {
    asm volatile("cp.async.cg.shared.global [%0], [%1], 16;" :: "r"(dst), "l"(src) : "memory");
}
#define CP_COMMIT() asm volatile("cp.async.commit_group;" ::: "memory")
#define CP_WAIT(n)  asm volatile("cp.async.wait_group %0;" :: "n"(n) : "memory")

__device__ __forceinline__ void ldsm4(uint32_t r[4], uint32_t addr) {
    asm volatile("ldmatrix.sync.aligned.m8n8.x4.shared.b16 {%0,%1,%2,%3}, [%4];"
                 : "=r"(r[0]), "=r"(r[1]), "=r"(r[2]), "=r"(r[3]) : "r"(addr));
}

__device__ __forceinline__ void mma_f16(float c[4], const uint32_t a[4],
                                        uint32_t b0, uint32_t b1) {
    asm volatile(
        "mma.sync.aligned.m16n8k16.row.col.f32.f16.f16.f32 "
        "{%0,%1,%2,%3}, {%4,%5,%6,%7}, {%8,%9}, {%0,%1,%2,%3};"
        : "+f"(c[0]), "+f"(c[1]), "+f"(c[2]), "+f"(c[3])
        : "r"(a[0]), "r"(a[1]), "r"(a[2]), "r"(a[3]), "r"(b0), "r"(b1));
}

// ---------------- prep: fp32 -> fp16 (rne) ----------------
__global__ void cvt_f16_kernel(const float* __restrict__ x, const float* __restrict__ w) {
    size_t i = (size_t)blockIdx.x * blockDim.x + threadIdx.x;  // over 2M float4
    float4 a = reinterpret_cast<const float4*>(x)[i];
    reinterpret_cast<__half2*>(g_xh)[2 * i + 0] = __floats2half2_rn(a.x, a.y);
    reinterpret_cast<__half2*>(g_xh)[2 * i + 1] = __floats2half2_rn(a.z, a.w);
    float4 b = reinterpret_cast<const float4*>(w)[i];
    reinterpret_cast<__half2*>(g_wh)[2 * i + 0] = __floats2half2_rn(b.x, b.y);
    reinterpret_cast<__half2*>(g_wh)[2 * i + 1] = __floats2half2_rn(b.z, b.w);
}

// ---------------- GEMM ----------------
// smem per stage: A[128][64h] then B^T[128][64h], 128B rows, XOR-16B swizzle:
// 16B-chunk c of row r stored at chunk (c ^ (r & 7)).

__device__ __forceinline__ void load_half(int tid, uint32_t sdst,
                                          const __half* __restrict__ G,
                                          size_t koff) {
#pragma unroll
    for (int q = 0; q < 4; q++) {            // 128 rows x 8 x 16B
        int idx = tid + q * 256;
        int row = idx >> 3, ch = idx & 7;
        uint32_t dst = sdst + (uint32_t)row * 128u + (uint32_t)((ch ^ (row & 7)) << 4);
        cp_async16(dst, G + (size_t)row * K_DIM + koff + ch * 8);
    }
}

__global__ __launch_bounds__(256, 2) void gemm_f16_kernel(float* __restrict__ out) {
    extern __shared__ __align__(1024) char smem[];
    uint32_t sbase = smem_u32(smem);
    int tid  = threadIdx.x;
    int wid  = tid >> 5;
    int lane = tid & 31;
    int wm = wid >> 2;        // 0..1  -> M offset wm*64
    int wn = wid & 3;         // 0..3  -> N offset wn*32
    // kk rotation: SMSP partners (wid, wid+4) offset by 2, plus per-CTA
    // rotation so the two co-resident CTAs on an SM are decorrelated too.
    int bid = blockIdx.y * 32 + blockIdx.x;
    uint32_t woff = (uint32_t)((((wid & 3) + ((wid >> 2) << 1)) + bid) & 3);

    const __half* Ag = g_xh + (size_t)blockIdx.y * BM * K_DIM;
    const __half* Bg = g_wh + (size_t)blockIdx.x * BN * K_DIM;

    // ldmatrix address components (verified fragment mapping from R4-R9):
    uint32_t a_row[4], a_xor[4];
#pragma unroll
    for (int mt = 0; mt < 4; mt++) {
        int row = wm * 64 + mt * 16 + (lane & 15);
        a_row[mt] = (uint32_t)row * 128u;
        a_xor[mt] = (uint32_t)(row & 7);
    }
    uint32_t ahi = (uint32_t)(lane >> 4);
    uint32_t b_row[2], b_xor[2];
#pragma unroll
    for (int nt2 = 0; nt2 < 2; nt2++) {
        int row = wn * 32 + nt2 * 16 + (lane & 7) + ((lane >> 4) << 3);
        b_row[nt2] = (uint32_t)row * 128u;
        b_xor[nt2] = (uint32_t)(row & 7);
    }
    uint32_t bhi = (uint32_t)((lane >> 3) & 1);

    float acc[4][4][4];
#pragma unroll
    for (int mt = 0; mt < 4; mt++)
#pragma unroll
        for (int nt = 0; nt < 4; nt++)
#pragma unroll
            for (int r = 0; r < 4; r++) acc[mt][nt][r] = 0.0f;

    // prologue: chunks 0..NSTAGE-2
    load_half(tid, sbase + 0 * STAGE_BYTES, Ag, 0);
    load_half(tid, sbase + 0 * STAGE_BYTES + A_BYTES, Bg, 0);
    CP_COMMIT();
    load_half(tid, sbase + 1 * STAGE_BYTES, Ag, BK);
    load_half(tid, sbase + 1 * STAGE_BYTES + A_BYTES, Bg, BK);
    CP_COMMIT();

    // incremental stage offsets: compute-stage and load-stage byte offsets
    uint32_t soff_c = 0;                               // stage of chunk i
    uint32_t soff_l = (NSTAGE - 1) * STAGE_BYTES;      // stage of chunk i+2
    size_t   lkoff  = (size_t)(NSTAGE - 1) * BK;       // gmem K offset of load

#pragma unroll 1
    for (int i = 0; i < NCHUNK; i++) {
        CP_WAIT(1);                 // chunk i resident (uniform commit count)
        __syncthreads();            // RAW chunk i; WAR proof for stage (i+2)%3

        uint32_t sa = sbase + soff_c;
        uint32_t sb = sa + A_BYTES;
        uint32_t sl = sbase + soff_l;
        bool do_load = i < NCHUNK - (NSTAGE - 1);

#pragma unroll
        for (int kk2 = 0; kk2 < 4; kk2++) {    // 4 x k16, rotated per warp/CTA
            uint32_t kk = ((uint32_t)kk2 + woff) & 3u;
            uint32_t af[4][4], bf[2][4];
#pragma unroll
            for (int mt = 0; mt < 4; mt++)
                ldsm4(af[mt], sa + a_row[mt] +
                      (((2u * kk + ahi) ^ a_xor[mt]) << 4));
#pragma unroll
            for (int nt2 = 0; nt2 < 2; nt2++)
                ldsm4(bf[nt2], sb + b_row[nt2] +
                      (((2u * kk + bhi) ^ b_xor[nt2]) << 4));
#pragma unroll
            for (int mt = 0; mt < 4; mt++)
#pragma unroll
                for (int nt = 0; nt < 4; nt++)
                    mma_f16(acc[mt][nt], af[mt],
                            bf[nt >> 1][(nt & 1) ? 2 : 0],
                            bf[nt >> 1][(nt & 1) ? 3 : 1]);

            // interleave next-stage loads with compute
            if (kk2 == 0 && do_load) load_half(tid, sl, Ag, lkoff);
            if (kk2 == 1 && do_load) load_half(tid, sl + A_BYTES, Bg, lkoff);
            if (kk2 == 1) CP_COMMIT();   // uniform group count (empty if !do_load)
        }

        // advance stage ring
        soff_c += STAGE_BYTES; if (soff_c == NSTAGE * STAGE_BYTES) soff_c = 0;
        soff_l += STAGE_BYTES; if (soff_l == NSTAGE * STAGE_BYTES) soff_l = 0;
        lkoff  += BK;
    }

    // epilogue: direct STG from fragments (c0,c1 contiguous; c2,c3 at row+8)
    int g = lane >> 2, tig = lane & 3;
    size_t orow0 = (size_t)(blockIdx.y * BM + wm * 64 + g) * O_DIM;
    int ocol0 = blockIdx.x * BN + wn * 32 + 2 * tig;
#pragma unroll
    for (int mt = 0; mt < 4; mt++) {
#pragma unroll
        for (int nt = 0; nt < 4; nt++) {
            size_t base = orow0 + (size_t)(mt * 16) * O_DIM + (ocol0 + nt * 8);
            *reinterpret_cast<float2*>(out + base) =
                make_float2(acc[mt][nt][0], acc[mt][nt][1]);
            *reinterpret_cast<float2*>(out + base + (size_t)8 * O_DIM) =
                make_float2(acc[mt][nt][2], acc[mt][nt][3]);
        }
    }
}

// ---------------- launch ----------------
extern "C" void kernel_launch(void* const* d_in, const int* in_sizes, int n_in,
                              void* d_out, int out_size) {
    const float* x = (const float*)d_in[0];   // [4096, 2048]
    const float* w = (const float*)d_in[1];   // [1, 4096, 2048]
    float* out = (float*)d_out;               // [4096, 4096]

    // 1) round both operands to nearest-fp16 (same mantissa as tf32)
    cvt_f16_kernel<<<(B_DIM * K_DIM / 4) / 256, 256>>>(x, w);

    // 2) fp16 mma.sync GEMM, fp32 accumulate
    cudaFuncSetAttribute(gemm_f16_kernel, cudaFuncAttributeMaxDynamicSharedMemorySize,
                         SMEM_TOTAL);
    dim3 grid(O_DIM / BN, B_DIM / BM);        // (32, 32) = 1024 CTAs
    gemm_f16_kernel<<<grid, 256, SMEM_TOTAL>>>(out);
}

// round 12
// speedup vs baseline: 1.5108x; 1.5108x over previous
#include <cuda_runtime.h>
#include <cuda_fp16.h>
#include <cstdint>

// ============================================================
// TorchRandomProject: out[4096,4096] = x[4096,2048] @ matrix[0][4096,2048]^T
// fp16 HMMA (same 10-bit mantissa as tf32 => same rel_err), fp32 accum.
// R12: EXACT revert to the R9 champion (168.7us): 128x128 tile, 2 CTA/SM,
// 3-stage cp.async, unroll-1 chunk loop, warp-level kk stagger (NO per-CTA
// bid rotation). R11's uniform 1.55x slowdown with unchanged pipe ratios is
// diagnosed as clock throttle (HBM GB/s dropped by the same 1.53x), not a
// code effect; this round re-validates the champion under current clocks.
// ============================================================

#define B_DIM   4096
#define K_DIM   2048
#define O_DIM   4096

// 32MB device scratch for fp16 operands
__device__ __half g_xh[(size_t)B_DIM * K_DIM];
__device__ __half g_wh[(size_t)O_DIM * K_DIM];

// ---------------- tile config ----------------
#define BM 128
#define BN 128
#define BK 64                       // K halfs per chunk (128B row)
#define NSTAGE 3
#define NCHUNK (K_DIM / BK)         // 32
#define A_BYTES (BM * BK * 2)       // 16384
#define B_BYTES (BN * BK * 2)       // 16384
#define STAGE_BYTES (A_BYTES + B_BYTES)      // 32768
#define SMEM_TOTAL (NSTAGE * STAGE_BYTES)    // 98304 (2 CTAs = 192KB/SM)

// ---------------- PTX helpers ----------------
__device__ __forceinline__ uint32_t smem_u32(const void* p) {
    uint32_t a;
    asm("{ .reg .u64 t; cvta.to.shared.u64 t, %1; cvt.u32.u64 %0, t; }" : "=r"(a) : "l"(p));
    return a;
}

__device__ __forceinline__ void cp_async16(uint32_t dst, const void* src) {
    asm volatile("cp.async.cg.shared.global [%0], [%1], 16;" :: "r"(dst), "l"(src) : "memory");
}
#define CP_COMMIT() asm volatile("cp.async.commit_group;" ::: "memory")
#define CP_WAIT(n)  asm volatile("cp.async.wait_group %0;" :: "n"(n) : "memory")

__device__ __forceinline__ void ldsm4(uint32_t r[4], uint32_t addr) {
    asm volatile("ldmatrix.sync.aligned.m8n8.x4.shared.b16 {%0,%1,%2,%3}, [%4];"
                 : "=r"(r[0]), "=r"(r[1]), "=r"(r[2]), "=r"(r[3]) : "r"(addr));
}

__device__ __forceinline__ void mma_f16(float c[4], const uint32_t a[4],
                                        uint32_t b0, uint32_t b1) {
    asm volatile(
        "mma.sync.aligned.m16n8k16.row.col.f32.f16.f16.f32 "
        "{%0,%1,%2,%3}, {%4,%5,%6,%7}, {%8,%9}, {%0,%1,%2,%3};"
        : "+f"(c[0]), "+f"(c[1]), "+f"(c[2]), "+f"(c[3])
        : "r"(a[0]), "r"(a[1]), "r"(a[2]), "r"(a[3]), "r"(b0), "r"(b1));
}

// ---------------- prep: fp32 -> fp16 (rne) ----------------
__global__ void cvt_f16_kernel(const float* __restrict__ x, const float* __restrict__ w) {
    size_t i = (size_t)blockIdx.x * blockDim.x + threadIdx.x;  // over 2M float4
    float4 a = reinterpret_cast<const float4*>(x)[i];
    reinterpret_cast<__half2*>(g_xh)[2 * i + 0] = __floats2half2_rn(a.x, a.y);
    reinterpret_cast<__half2*>(g_xh)[2 * i + 1] = __floats2half2_rn(a.z, a.w);
    float4 b = reinterpret_cast<const float4*>(w)[i];
    reinterpret_cast<__half2*>(g_wh)[2 * i + 0] = __floats2half2_rn(b.x, b.y);
    reinterpret_cast<__half2*>(g_wh)[2 * i + 1] = __floats2half2_rn(b.z, b.w);
}

// ---------------- GEMM ----------------
// smem per stage: A[128][64h] then B^T[128][64h], 128B rows, XOR-16B swizzle:
// 16B-chunk c of row r stored at chunk (c ^ (r & 7)).

__device__ __forceinline__ void load_half(int tid, uint32_t sdst,
                                          const __half* __restrict__ G,
                                          size_t koff) {
#pragma unroll
    for (int q = 0; q < 4; q++) {            // 128 rows x 8 x 16B
        int idx = tid + q * 256;
        int row = idx >> 3, ch = idx & 7;
        uint32_t dst = sdst + (uint32_t)row * 128u + (uint32_t)((ch ^ (row & 7)) << 4);
        cp_async16(dst, G + (size_t)row * K_DIM + koff + ch * 8);
    }
}

__global__ __launch_bounds__(256, 2) void gemm_f16_kernel(float* __restrict__ out) {
    extern __shared__ __align__(1024) char smem[];
    uint32_t sbase = smem_u32(smem);
    int tid  = threadIdx.x;
    int wid  = tid >> 5;
    int lane = tid & 31;
    int wm = wid >> 2;        // 0..1  -> M offset wm*64
    int wn = wid & 3;         // 0..3  -> N offset wn*32
    // kk rotation: warps sharing an SMSP (wid, wid+4) get offsets s and s+2
    uint32_t woff = (uint32_t)(((wid & 3) + ((wid >> 2) << 1)) & 3);

    const __half* Ag = g_xh + (size_t)blockIdx.y * BM * K_DIM;
    const __half* Bg = g_wh + (size_t)blockIdx.x * BN * K_DIM;

    // ldmatrix address components (verified fragment mapping from R4-R9):
    uint32_t a_row[4], a_xor[4];
#pragma unroll
    for (int mt = 0; mt < 4; mt++) {
        int row = wm * 64 + mt * 16 + (lane & 15);
        a_row[mt] = (uint32_t)row * 128u;
        a_xor[mt] = (uint32_t)(row & 7);
    }
    uint32_t ahi = (uint32_t)(lane >> 4);
    uint32_t b_row[2], b_xor[2];
#pragma unroll
    for (int nt2 = 0; nt2 < 2; nt2++) {
        int row = wn * 32 + nt2 * 16 + (lane & 7) + ((lane >> 4) << 3);
        b_row[nt2] = (uint32_t)row * 128u;
        b_xor[nt2] = (uint32_t)(row & 7);
    }
    uint32_t bhi = (uint32_t)((lane >> 3) & 1);

    float acc[4][4][4];
#pragma unroll
    for (int mt = 0; mt < 4; mt++)
#pragma unroll
        for (int nt = 0; nt < 4; nt++)
#pragma unroll
            for (int r = 0; r < 4; r++) acc[mt][nt][r] = 0.0f;

    // prologue: chunks 0..NSTAGE-2
    load_half(tid, sbase + 0 * STAGE_BYTES, Ag, 0);
    load_half(tid, sbase + 0 * STAGE_BYTES + A_BYTES, Bg, 0);
    CP_COMMIT();
    load_half(tid, sbase + 1 * STAGE_BYTES, Ag, BK);
    load_half(tid, sbase + 1 * STAGE_BYTES + A_BYTES, Bg, BK);
    CP_COMMIT();

    // incremental stage offsets: compute-stage and load-stage byte offsets
    uint32_t soff_c = 0;                               // stage of chunk i
    uint32_t soff_l = (NSTAGE - 1) * STAGE_BYTES;      // stage of chunk i+2
    size_t   lkoff  = (size_t)(NSTAGE - 1) * BK;       // gmem K offset of load

#pragma unroll 1
    for (int i = 0; i < NCHUNK; i++) {
        CP_WAIT(1);                 // chunk i resident (uniform commit count)
        __syncthreads();            // RAW chunk i; WAR proof for stage (i+2)%3

        uint32_t sa = sbase + soff_c;
        uint32_t sb = sa + A_BYTES;
        uint32_t sl = sbase + soff_l;
        bool do_load = i < NCHUNK - (NSTAGE - 1);

#pragma unroll
        for (int kk2 = 0; kk2 < 4; kk2++) {    // 4 x k16, rotated per warp
            uint32_t kk = ((uint32_t)kk2 + woff) & 3u;
            uint32_t af[4][4], bf[2][4];
#pragma unroll
            for (int mt = 0; mt < 4; mt++)
                ldsm4(af[mt], sa + a_row[mt] +
                      (((2u * kk + ahi) ^ a_xor[mt]) << 4));
#pragma unroll
            for (int nt2 = 0; nt2 < 2; nt2++)
                ldsm4(bf[nt2], sb + b_row[nt2] +
                      (((2u * kk + bhi) ^ b_xor[nt2]) << 4));
#pragma unroll
            for (int mt = 0; mt < 4; mt++)
#pragma unroll
                for (int nt = 0; nt < 4; nt++)
                    mma_f16(acc[mt][nt], af[mt],
                            bf[nt >> 1][(nt & 1) ? 2 : 0],
                            bf[nt >> 1][(nt & 1) ? 3 : 1]);

            // interleave next-stage loads with compute
            if (kk2 == 0 && do_load) load_half(tid, sl, Ag, lkoff);
            if (kk2 == 1 && do_load) load_half(tid, sl + A_BYTES, Bg, lkoff);
            if (kk2 == 1) CP_COMMIT();   // uniform group count (empty if !do_load)
        }

        // advance stage ring
        soff_c += STAGE_BYTES; if (soff_c == NSTAGE * STAGE_BYTES) soff_c = 0;
        soff_l += STAGE_BYTES; if (soff_l == NSTAGE * STAGE_BYTES) soff_l = 0;
        lkoff  += BK;
    }

    // epilogue: direct STG from fragments (c0,c1 contiguous; c2,c3 at row+8)
    int g = lane >> 2, tig = lane & 3;
    size_t orow0 = (size_t)(blockIdx.y * BM + wm * 64 + g) * O_DIM;
    int ocol0 = blockIdx.x * BN + wn * 32 + 2 * tig;
#pragma unroll
    for (int mt = 0; mt < 4; mt++) {
#pragma unroll
        for (int nt = 0; nt < 4; nt++) {
            size_t base = orow0 + (size_t)(mt * 16) * O_DIM + (ocol0 + nt * 8);
            *reinterpret_cast<float2*>(out + base) =
                make_float2(acc[mt][nt][0], acc[mt][nt][1]);
            *reinterpret_cast<float2*>(out + base + (size_t)8 * O_DIM) =
                make_float2(acc[mt][nt][2], acc[mt][nt][3]);
        }
    }
}

// ---------------- launch ----------------
extern "C" void kernel_launch(void* const* d_in, const int* in_sizes, int n_in,
                              void* d_out, int out_size) {
    const float* x = (const float*)d_in[0];   // [4096, 2048]
    const float* w = (const float*)d_in[1];   // [1, 4096, 2048]
    float* out = (float*)d_out;               // [4096, 4096]

    // 1) round both operands to nearest-fp16 (same mantissa as tf32)
    cvt_f16_kernel<<<(B_DIM * K_DIM / 4) / 256, 256>>>(x, w);

    // 2) fp16 mma.sync GEMM, fp32 accumulate
    cudaFuncSetAttribute(gemm_f16_kernel, cudaFuncAttributeMaxDynamicSharedMemorySize,
                         SMEM_TOTAL);
    dim3 grid(O_DIM / BN, B_DIM / BM);        // (32, 32) = 1024 CTAs
    gemm_f16_kernel<<<grid, 256, SMEM_TOTAL>>>(out);
}

// round 14
// speedup vs baseline: 1.5654x; 1.0361x over previous
#include <cuda_runtime.h>
#include <cuda_fp16.h>
#include <cstdint>

// ============================================================
// TorchRandomProject: out[4096,4096] = x[4096,2048] @ matrix[0][4096,2048]^T
// fp16 HMMA (same 10-bit mantissa as tf32 => same rel_err), fp32 accum.
// R14: R13 mbarrier producer/consumer pipeline with the deadlock fixed:
// cp.async.mbarrier.arrive needs .noinc so the async completion COUNTS
// toward the expected 256 arrivals (default form is count-neutral:
// +1 pending then -1 on completion => phase never completes => R13 hang).
// Compute body/tile config identical to the 168.1us champion.
// ============================================================

#define B_DIM   4096
#define K_DIM   2048
#define O_DIM   4096

// 32MB device scratch for fp16 operands
__device__ __half g_xh[(size_t)B_DIM * K_DIM];
__device__ __half g_wh[(size_t)O_DIM * K_DIM];

// ---------------- tile config ----------------
#define BM 128
#define BN 128
#define BK 64                       // K halfs per chunk (128B row)
#define NSTAGE 3
#define NCHUNK (K_DIM / BK)         // 32
#define A_BYTES (BM * BK * 2)       // 16384
#define B_BYTES (BN * BK * 2)       // 16384
#define STAGE_BYTES (A_BYTES + B_BYTES)      // 32768 (= 1<<15)
#define SM_DATA0 1024               // stages start here (mbarriers below)
#define SMEM_TOTAL (SM_DATA0 + NSTAGE * STAGE_BYTES)  // 99328 (x2 CTA ok)

// ---------------- PTX helpers ----------------
__device__ __forceinline__ uint32_t smem_u32(const void* p) {
    uint32_t a;
    asm("{ .reg .u64 t; cvta.to.shared.u64 t, %1; cvt.u32.u64 %0, t; }" : "=r"(a) : "l"(p));
    return a;
}

__device__ __forceinline__ void cp_async16(uint32_t dst, const void* src) {
    asm volatile("cp.async.cg.shared.global [%0], [%1], 16;" :: "r"(dst), "l"(src) : "memory");
}

#define MBARRIER_INIT(addr, count) \
    asm volatile("mbarrier.init.shared.b64 [%0], %1;" :: "r"((uint32_t)(addr)), "r"((uint32_t)(count)) : "memory")

// .noinc: the deferred arrive (fires when this thread's prior cp.asyncs
// complete) DECREMENTS the pending count, i.e. counts toward the expected
// arrivals. (Default form pre-increments and is count-neutral -> deadlock.)
#define CP_ASYNC_MBAR_ARRIVE_NOINC(addr) \
    asm volatile("cp.async.mbarrier.arrive.noinc.shared.b64 [%0];" :: "r"((uint32_t)(addr)) : "memory")

#define MBARRIER_ARRIVE(addr) \
    asm volatile("mbarrier.arrive.shared.b64 _, [%0];" :: "r"((uint32_t)(addr)) : "memory")

#define MBARRIER_WAIT_PARITY(addr, parity) do { \
    uint32_t _mbar = (uint32_t)(addr); \
    uint32_t _par = (uint32_t)(parity); \
    uint32_t _done; \
    asm volatile("{\n\t.reg .pred p;\n\t" \
        "mbarrier.try_wait.parity.acquire.cta.shared::cta.b64 p, [%1], %2;\n\t" \
        "selp.b32 %0, 1, 0, p;\n\t}" : "=r"(_done) : "r"(_mbar), "r"(_par) : "memory"); \
    if (!_done) { \
        asm volatile("{\n\t.reg .pred P1;\n\t" \
            "WL_%=:\n\t" \
            "mbarrier.try_wait.parity.acquire.cta.shared::cta.b64 P1, [%0], %1, 0x989680;\n\t" \
            "@P1 bra.uni WD_%=;\n\t" \
            "bra.uni WL_%=;\n\t" \
            "WD_%=:\n\t}" :: "r"(_mbar), "r"(_par) : "memory"); \
    } \
} while (0)

__device__ __forceinline__ void ldsm4(uint32_t r[4], uint32_t addr) {
    asm volatile("ldmatrix.sync.aligned.m8n8.x4.shared.b16 {%0,%1,%2,%3}, [%4];"
                 : "=r"(r[0]), "=r"(r[1]), "=r"(r[2]), "=r"(r[3]) : "r"(addr));
}

__device__ __forceinline__ void mma_f16(float c[4], const uint32_t a[4],
                                        uint32_t b0, uint32_t b1) {
    asm volatile(
        "mma.sync.aligned.m16n8k16.row.col.f32.f16.f16.f32 "
        "{%0,%1,%2,%3}, {%4,%5,%6,%7}, {%8,%9}, {%0,%1,%2,%3};"
        : "+f"(c[0]), "+f"(c[1]), "+f"(c[2]), "+f"(c[3])
        : "r"(a[0]), "r"(a[1]), "r"(a[2]), "r"(a[3]), "r"(b0), "r"(b1));
}

// ---------------- prep: fp32 -> fp16 (rne) ----------------
__global__ void cvt_f16_kernel(const float* __restrict__ x, const float* __restrict__ w) {
    size_t i = (size_t)blockIdx.x * blockDim.x + threadIdx.x;  // over 2M float4
    float4 a = reinterpret_cast<const float4*>(x)[i];
    reinterpret_cast<__half2*>(g_xh)[2 * i + 0] = __floats2half2_rn(a.x, a.y);
    reinterpret_cast<__half2*>(g_xh)[2 * i + 1] = __floats2half2_rn(a.z, a.w);
    float4 b = reinterpret_cast<const float4*>(w)[i];
    reinterpret_cast<__half2*>(g_wh)[2 * i + 0] = __floats2half2_rn(b.x, b.y);
    reinterpret_cast<__half2*>(g_wh)[2 * i + 1] = __floats2half2_rn(b.z, b.w);
}

// ---------------- GEMM ----------------
// mbarriers: full[s] = sbase + s*16 (count 256, .noinc arrive-on per thread),
// empty[s] = +8 (count 8, lane-0 arrive per warp).
// stage data at sbase + SM_DATA0; A then B, 128B rows, XOR-16B swizzle.

__device__ __forceinline__ void load_half(int tid, uint32_t sdst,
                                          const __half* __restrict__ G,
                                          size_t koff) {
#pragma unroll
    for (int q = 0; q < 4; q++) {            // 128 rows x 8 x 16B
        int idx = tid + q * 256;
        int row = idx >> 3, ch = idx & 7;
        uint32_t dst = sdst + (uint32_t)row * 128u + (uint32_t)((ch ^ (row & 7)) << 4);
        cp_async16(dst, G + (size_t)row * K_DIM + koff + ch * 8);
    }
}

__global__ __launch_bounds__(256, 2) void gemm_f16_kernel(float* __restrict__ out) {
    extern __shared__ __align__(1024) char smem[];
    uint32_t sbase = smem_u32(smem);
    uint32_t sdata = sbase + SM_DATA0;
    int tid  = threadIdx.x;
    int wid  = tid >> 5;
    int lane = tid & 31;
    int wm = wid >> 2;        // 0..1  -> M offset wm*64
    int wn = wid & 3;         // 0..3  -> N offset wn*32
    // kk rotation: warps sharing an SMSP (wid, wid+4) get offsets s and s+2
    uint32_t woff = (uint32_t)(((wid & 3) + ((wid >> 2) << 1)) & 3);

    const __half* Ag = g_xh + (size_t)blockIdx.y * BM * K_DIM;
    const __half* Bg = g_wh + (size_t)blockIdx.x * BN * K_DIM;

    if (tid == 0) {
#pragma unroll
        for (int s = 0; s < NSTAGE; s++) {
            MBARRIER_INIT(sbase + s * 16, 256);     // full: .noinc arrive per thread
            MBARRIER_INIT(sbase + s * 16 + 8, 8);   // empty: one arrive per warp
        }
    }
    __syncthreads();

    // ldmatrix address components (verified fragment mapping from R4-R12):
    uint32_t a_row[4], a_xor[4];
#pragma unroll
    for (int mt = 0; mt < 4; mt++) {
        int row = wm * 64 + mt * 16 + (lane & 15);
        a_row[mt] = (uint32_t)row * 128u;
        a_xor[mt] = (uint32_t)(row & 7);
    }
    uint32_t ahi = (uint32_t)(lane >> 4);
    uint32_t b_row[2], b_xor[2];
#pragma unroll
    for (int nt2 = 0; nt2 < 2; nt2++) {
        int row = wn * 32 + nt2 * 16 + (lane & 7) + ((lane >> 4) << 3);
        b_row[nt2] = (uint32_t)row * 128u;
        b_xor[nt2] = (uint32_t)(row & 7);
    }
    uint32_t bhi = (uint32_t)((lane >> 3) & 1);

    float acc[4][4][4];
#pragma unroll
    for (int mt = 0; mt < 4; mt++)
#pragma unroll
        for (int nt = 0; nt < 4; nt++)
#pragma unroll
            for (int r = 0; r < 4; r++) acc[mt][nt][r] = 0.0f;

    // prologue: fill stages 0,1 (first fills: no empty wait needed)
    load_half(tid, sdata + 0 * STAGE_BYTES, Ag, 0);
    load_half(tid, sdata + 0 * STAGE_BYTES + A_BYTES, Bg, 0);
    CP_ASYNC_MBAR_ARRIVE_NOINC(sbase + 0 * 16);
    load_half(tid, sdata + 1 * STAGE_BYTES, Ag, BK);
    load_half(tid, sdata + 1 * STAGE_BYTES + A_BYTES, Bg, BK);
    CP_ASYNC_MBAR_ARRIVE_NOINC(sbase + 1 * 16);

    // pipeline cursors: consumer (chunk i), producer (chunk i+2)
    uint32_t soff_c = 0;                      // stage byte-offset of chunk i
    uint32_t p_full = 0;                      // full parity = (i/3)&1
    uint32_t soff_l = (NSTAGE - 1) * STAGE_BYTES;  // stage of chunk i+2
    uint32_t p_empty = 1;                     // first empty-wait passes
    size_t   lkoff  = (size_t)(NSTAGE - 1) * BK;

#pragma unroll 1
    for (int i = 0; i < NCHUNK; i++) {
        uint32_t mb = sbase + (soff_c >> 15) * 16;
        MBARRIER_WAIT_PARITY(mb, p_full);     // chunk i data visible (acquire)

        uint32_t sa = sdata + soff_c;
        uint32_t sb = sa + A_BYTES;

#pragma unroll
        for (int kk2 = 0; kk2 < 4; kk2++) {   // 4 x k16, rotated per warp
            uint32_t kk = ((uint32_t)kk2 + woff) & 3u;
            uint32_t af[4][4], bf[2][4];
#pragma unroll
            for (int mt = 0; mt < 4; mt++)
                ldsm4(af[mt], sa + a_row[mt] +
                      (((2u * kk + ahi) ^ a_xor[mt]) << 4));
#pragma unroll
            for (int nt2 = 0; nt2 < 2; nt2++)
                ldsm4(bf[nt2], sb + b_row[nt2] +
                      (((2u * kk + bhi) ^ b_xor[nt2]) << 4));
#pragma unroll
            for (int mt = 0; mt < 4; mt++)
#pragma unroll
                for (int nt = 0; nt < 4; nt++)
                    mma_f16(acc[mt][nt], af[mt],
                            bf[nt >> 1][(nt & 1) ? 2 : 0],
                            bf[nt >> 1][(nt & 1) ? 3 : 1]);
        }

        // this warp is done reading stage of chunk i -> release it
        __syncwarp();
        if (lane == 0) MBARRIER_ARRIVE(mb + 8);

        // producer: fill stage for chunk i+2 (waits consumers of chunk i-1)
        if (i < NCHUNK - (NSTAGE - 1)) {
            uint32_t mbl = sbase + (soff_l >> 15) * 16;
            MBARRIER_WAIT_PARITY(mbl + 8, p_empty);   // stage free (acquire)
            uint32_t sl = sdata + soff_l;
            load_half(tid, sl, Ag, lkoff);
            load_half(tid, sl + A_BYTES, Bg, lkoff);
            CP_ASYNC_MBAR_ARRIVE_NOINC(mbl);
        }

        // advance cursors (flip parity on ring wrap)
        soff_c += STAGE_BYTES;
        if (soff_c == NSTAGE * STAGE_BYTES) { soff_c = 0; p_full ^= 1; }
        soff_l += STAGE_BYTES;
        if (soff_l == NSTAGE * STAGE_BYTES) { soff_l = 0; p_empty ^= 1; }
        lkoff += BK;
    }

    // epilogue: direct STG from fragments (c0,c1 contiguous; c2,c3 at row+8)
    int g = lane >> 2, tig = lane & 3;
    size_t orow0 = (size_t)(blockIdx.y * BM + wm * 64 + g) * O_DIM;
    int ocol0 = blockIdx.x * BN + wn * 32 + 2 * tig;
#pragma unroll
    for (int mt = 0; mt < 4; mt++) {
#pragma unroll
        for (int nt = 0; nt < 4; nt++) {
            size_t base = orow0 + (size_t)(mt * 16) * O_DIM + (ocol0 + nt * 8);
            *reinterpret_cast<float2*>(out + base) =
                make_float2(acc[mt][nt][0], acc[mt][nt][1]);
            *reinterpret_cast<float2*>(out + base + (size_t)8 * O_DIM) =
                make_float2(acc[mt][nt][2], acc[mt][nt][3]);
        }
    }
}

// ---------------- launch ----------------
extern "C" void kernel_launch(void* const* d_in, const int* in_sizes, int n_in,
                              void* d_out, int out_size) {
    const float* x = (const float*)d_in[0];   // [4096, 2048]
    const float* w = (const float*)d_in[1];   // [1, 4096, 2048]
    float* out = (float*)d_out;               // [4096, 4096]

    // 1) round both operands to nearest-fp16 (same mantissa as tf32)
    cvt_f16_kernel<<<(B_DIM * K_DIM / 4) / 256, 256>>>(x, w);

    // 2) fp16 mma.sync GEMM, fp32 accumulate, mbarrier pipeline
    cudaFuncSetAttribute(gemm_f16_kernel, cudaFuncAttributeMaxDynamicSharedMemorySize,
                         SMEM_TOTAL);
    dim3 grid(O_DIM / BN, B_DIM / BM);        // (32, 32) = 1024 CTAs
    gemm_f16_kernel<<<grid, 256, SMEM_TOTAL>>>(out);
}